// round 4
// baseline (speedup 1.0000x reference)
#include <cuda_runtime.h>
#include <math.h>

// BarycentricCoordinates: V=6000 x (R*A)=40 items, N=16 projections each.
// One thread per item; 40 consecutive threads share one v's projections.
//
// Bit-exactness model vs the eagerly-dispatched XLA fp32 reference:
//  - einsum dot products (K=2) lower to fma chains with acc=0:
//      dot = __fmaf_rn(y, y', __fmul_rn(x, x'))          [form B]
//  - all other elementwise ops are separate XLA kernels -> strict IEEE
//    mul/sub/div/sqrt with NO contraction                [form A]
// The argmin's within-pair cell choice compares values 1 ulp apart, so these
// rounding patterns must be reproduced exactly.

#define MULF(a,b)   __fmul_rn((a),(b))
#define ADDF(a,b)   __fadd_rn((a),(b))
#define SUBF(a,b)   __fsub_rn((a),(b))
#define DIVF(a,b)   __fdiv_rn((a),(b))
#define DOT2(ax,ay,bx,by) __fmaf_rn((ay),(by), __fmul_rn((ax),(bx)))

__global__ __launch_bounds__(128)
void bc_kernel(const float* __restrict__ tmpl,
               const float* __restrict__ proj,
               float* __restrict__ out, int V)
{
    const int RA = 40;
    int gid = blockIdx.x * blockDim.x + threadIdx.x;
    if (gid >= V * RA) return;
    int v  = gid / RA;
    int ra = gid - v * RA;

    float tx = __ldg(tmpl + 2 * ra);
    float ty = __ldg(tmpl + 2 * ra + 1);

    float px[16], py[16];
    const float4* pp = (const float4*)(proj + (size_t)v * 32);
    #pragma unroll
    for (int k = 0; k < 8; k++) {
        float4 q = __ldg(pp + k);
        px[2*k]   = q.x; py[2*k]   = q.y;
        px[2*k+1] = q.z; py[2*k+1] = q.w;
    }

    // dist = sqrt(x^2 + y^2): square kernel + reduce(add) + sqrt -> strict IEEE
    float dist[16];
    #pragma unroll
    for (int i = 0; i < 16; i++) {
        float dx = SUBF(tx, px[i]), dy = SUBF(ty, py[i]);
        dist[i] = __fsqrt_rn(ADDF(MULF(dx,dx), MULF(dy,dy)));
    }

    // Stable two-min scan: closest (bi) and 2nd-closest (si)
    float bd = dist[0], bx = px[0], by = py[0], sd = INFINITY;
    int bi = 0, si = 0;
    #pragma unroll
    for (int i = 1; i < 16; i++) {
        if (dist[i] < bd) {
            sd = bd; si = bi;
            bd = dist[i]; bi = i; bx = px[i]; by = py[i];
        } else if (dist[i] < sd) {
            sd = dist[i]; si = i;
        }
    }

    float v2x = SUBF(tx, bx), v2y = SUBF(ty, by);
    // einsum-derived quantities: fma form (B)
    float ex[16], ey[16], d00[16], d02[16];
    #pragma unroll
    for (int i = 0; i < 16; i++) {
        ex[i]  = SUBF(px[i], bx);
        ey[i]  = SUBF(py[i], by);
        d00[i] = DOT2(ex[i], ey[i], ex[i], ey[i]);
        d02[i] = DOT2(ex[i], ey[i], v2x, v2y);
    }

    float bestS = INFINITY;
    float w0 = 0.f, w1 = 0.f, w2 = 0.f;
    int   o1 = si, o2 = si;

    #pragma unroll
    for (int i = 0; i < 15; i++) {
        #pragma unroll
        for (int j = i + 1; j < 16; j++) {
            float d01 = DOT2(ex[i], ey[i], ex[j], ey[j]);          // einsum: fma form
            float den = SUBF(MULF(d00[i],d00[j]), MULF(d01,d01));  // elementwise: IEEE
            if (den == 0.0f) den = 1e-10f;                         // reference patch
            float nA = SUBF(MULF(d02[i],d00[j]), MULF(d01,d02[j])); // p2 num (i-first)
            float nB = SUBF(MULF(d00[i],d02[j]), MULF(d01,d02[i])); // p1 num (i-first)
            bool cand = (den > 0.0f) ? (nA > 0.0f && nB > 0.0f)
                                     : (nA < 0.0f && nB < 0.0f);
            if (cand) {
                float pA = DIVF(nA, den);                // p2 of i-first cell
                float pB = DIVF(nB, den);                // p1 of i-first cell
                float m2  = fmaxf(MULF(pA,pA), MULF(pB,pB));
                float p0i = SUBF(SUBF(1.0f, pA), pB);    // i-first cell p0
                float p0j = SUBF(SUBF(1.0f, pB), pA);    // j-first cell p0
                float siS = (p0i > 0.f) ? fmaxf(MULF(p0i,p0i), m2) : INFINITY;
                float sjS = (p0j > 0.f) ? fmaxf(MULF(p0j,p0j), m2) : INFINITY;

                bool iFirst = (dist[i] <= dist[j]);      // rank order (stable ties)
                float sLow  = iFirst ? siS : sjS;        // lower flat-index cell
                float sHigh = iFirst ? sjS : siS;
                bool pickLow = (sLow <= sHigh);          // argmin tie -> lower flat
                float s = pickLow ? sLow : sHigh;

                if (s < bestS) {
                    bestS = s;
                    bool icell = pickLow ? iFirst : !iFirst;
                    if (icell) { w0 = p0i; w1 = pA; w2 = pB; o1 = i; o2 = j; }
                    else       { w0 = p0j; w1 = pB; w2 = pA; o1 = j; o2 = i; }
                }
            }
        }
    }

    if (!(bestS < INFINITY)) {      // all-INF fallback: argmin -> diagonal cell 0
        w0 = 0.f; w1 = 0.f; w2 = 0.f; o1 = si; o2 = si;
    }

    float* ow = out + (size_t)gid * 3;
    ow[0] = w0; ow[1] = w1; ow[2] = w2;
    float* oi = out + (size_t)V * RA * 3 + (size_t)gid * 3;
    oi[0] = (float)bi; oi[1] = (float)o1; oi[2] = (float)o2;
}

extern "C" void kernel_launch(void* const* d_in, const int* in_sizes, int n_in,
                              void* d_out, int out_size)
{
    const float* tmpl = (const float*)d_in[0];   // (5,8,2) = 80 floats
    const float* proj = (const float*)d_in[1];   // (V,16,2)
    int V = in_sizes[1] / 32;
    int total = V * 40;
    int threads = 128;
    int blocks = (total + threads - 1) / threads;
    bc_kernel<<<blocks, threads>>>(tmpl, proj, (float*)d_out, V);
}

// round 5
// speedup vs baseline: 1.2365x; 1.2365x over previous
#include <cuda_runtime.h>
#include <math.h>

// BarycentricCoordinates: V=6000 x (R*A)=40 items, N=16 projections each.
// One thread per item.
//
// Bit-exactness model (validated in R4, rel_err == 0.0):
//  - einsum dot products (K=2): dot = __fmaf_rn(y,y', __fmul_rn(x,x'))
//  - all other elementwise ops: strict IEEE mul/sub/div/sqrt, no contraction.
//
// R5 restructure: the hot 120-pair loop is branch-free and DIVISION-FREE.
// Scores are ordered via cross-multiplication (sNum/den^2 form); sign gates on
// nA/nB/den are exact; the p0>0 gate uses p0n = den-nA-nB with a conservative
// margin (borderline pairs are ACCEPTED). The top-2 pairs are re-evaluated
// bit-exactly in the epilogue (exact divides + exact two-cell argmin), so any
// approx-ordering ambiguity within ~1e-7 relative is resolved exactly.

#define MULF(a,b)   __fmul_rn((a),(b))
#define ADDF(a,b)   __fadd_rn((a),(b))
#define SUBF(a,b)   __fsub_rn((a),(b))
#define DIVF(a,b)   __fdiv_rn((a),(b))
#define DOT2(ax,ay,bx,by) __fmaf_rn((ay),(by), __fmul_rn((ax),(bx)))

__global__ __launch_bounds__(128)
void bc_kernel(const float* __restrict__ tmpl,
               const float* __restrict__ proj,
               float* __restrict__ out, int V)
{
    const int RA = 40;
    int gid = blockIdx.x * blockDim.x + threadIdx.x;
    if (gid >= V * RA) return;
    int v  = gid / RA;
    int ra = gid - v * RA;

    float tx = __ldg(tmpl + 2 * ra);
    float ty = __ldg(tmpl + 2 * ra + 1);

    float px[16], py[16];
    const float4* pp = (const float4*)(proj + (size_t)v * 32);
    #pragma unroll
    for (int k = 0; k < 8; k++) {
        float4 q = __ldg(pp + k);
        px[2*k]   = q.x; py[2*k]   = q.y;
        px[2*k+1] = q.z; py[2*k+1] = q.w;
    }

    // dist: strict IEEE (matches reference fp32 norm bitwise)
    float dist[16];
    #pragma unroll
    for (int i = 0; i < 16; i++) {
        float dx = SUBF(tx, px[i]), dy = SUBF(ty, py[i]);
        dist[i] = __fsqrt_rn(ADDF(MULF(dx,dx), MULF(dy,dy)));
    }

    // Stable two-min scan: closest (bi) and 2nd-closest (si)
    float bd = dist[0], bx = px[0], by = py[0], sd = INFINITY;
    int bi = 0, si = 0;
    #pragma unroll
    for (int i = 1; i < 16; i++) {
        if (dist[i] < bd) {
            sd = bd; si = bi;
            bd = dist[i]; bi = i; bx = px[i]; by = py[i];
        } else if (dist[i] < sd) {
            sd = dist[i]; si = i;
        }
    }

    float v2x = SUBF(tx, bx), v2y = SUBF(ty, by);
    float ex[16], ey[16], d00[16], d02[16];
    #pragma unroll
    for (int i = 0; i < 16; i++) {
        ex[i]  = SUBF(px[i], bx);
        ey[i]  = SUBF(py[i], by);
        d00[i] = DOT2(ex[i], ey[i], ex[i], ey[i]);
        d02[i] = DOT2(ex[i], ey[i], v2x, v2y);
    }

    // ---- approximate top-2 pair search: branch-free, division-free ----
    float sN1 = INFINITY, dd1 = 1.0f; int id1 = -1;
    float sN2 = INFINITY, dd2 = 1.0f; int id2 = -1;

    #pragma unroll
    for (int i = 0; i < 15; i++) {
        #pragma unroll
        for (int j = i + 1; j < 16; j++) {
            float d01 = DOT2(ex[i], ey[i], ex[j], ey[j]);           // exact bits
            float den = SUBF(MULF(d00[i],d00[j]), MULF(d01,d01));   // exact bits
            den = (den == 0.0f) ? 1e-10f : den;
            float nA = SUBF(MULF(d02[i],d00[j]), MULF(d01,d02[j])); // exact bits
            float nB = SUBF(MULF(d00[i],d02[j]), MULF(d01,d02[i])); // exact bits
            bool denPos = den > 0.0f;
            bool cand = denPos ? (nA > 0.0f && nB > 0.0f)
                               : (nA < 0.0f && nB < 0.0f);
            float p0n = den - nA - nB;            // ~ p0 * den (approx ok)
            float thr = 1e-5f * (fabsf(den) + fabsf(nA) + fabsf(nB));
            bool p0ok = denPos ? (p0n > -thr) : (p0n < thr);  // conservative
            float sNum = fmaxf(fmaxf(nA*nA, nB*nB), p0n*p0n);
            float den2 = den * den;
            float s = (cand && p0ok) ? sNum : INFINITY;
            int code = i * 16 + j;
            // cross-multiplied ordering: s/den2 < sNx/ddx
            bool b1 = s * dd1 < sN1 * den2;
            bool b2 = s * dd2 < sN2 * den2;
            sN2 = b1 ? sN1 : (b2 ? s    : sN2);
            dd2 = b1 ? dd1 : (b2 ? den2 : dd2);
            id2 = b1 ? id1 : (b2 ? code : id2);
            sN1 = b1 ? s    : sN1;
            dd1 = b1 ? den2 : dd1;
            id1 = b1 ? code : id1;
        }
    }

    // ---- exact epilogue: re-evaluate top-2 candidates bit-exactly ----
    float w0 = 0.f, w1 = 0.f, w2 = 0.f;
    int   o1 = si, o2 = si;
    float bestS = INFINITY;

    #pragma unroll
    for (int c = 0; c < 2; c++) {
        int code = (c == 0) ? id1 : id2;
        if (code >= 0) {
            int ip = code >> 4, jp = code & 15;
            float exi=0,eyi=0,d00i=0,d02i=0,di=0;
            float exj=0,eyj=0,d00j=0,d02j=0,dj=0;
            #pragma unroll
            for (int k = 0; k < 16; k++) {
                bool a = (k == ip), b = (k == jp);
                exi  = a ? ex[k]  : exi;  eyi  = a ? ey[k]  : eyi;
                d00i = a ? d00[k] : d00i; d02i = a ? d02[k] : d02i;
                di   = a ? dist[k]: di;
                exj  = b ? ex[k]  : exj;  eyj  = b ? ey[k]  : eyj;
                d00j = b ? d00[k] : d00j; d02j = b ? d02[k] : d02j;
                dj   = b ? dist[k]: dj;
            }
            float d01 = DOT2(exi, eyi, exj, eyj);
            float den = SUBF(MULF(d00i,d00j), MULF(d01,d01));
            if (den == 0.0f) den = 1e-10f;
            float nA = SUBF(MULF(d02i,d00j), MULF(d01,d02j));
            float nB = SUBF(MULF(d00i,d02j), MULF(d01,d02i));
            bool candx = (den > 0.0f) ? (nA > 0.0f && nB > 0.0f)
                                      : (nA < 0.0f && nB < 0.0f);
            if (candx) {
                float pA = DIVF(nA, den);                 // exact IEEE divide
                float pB = DIVF(nB, den);
                float m2  = fmaxf(MULF(pA,pA), MULF(pB,pB));
                float p0i = SUBF(SUBF(1.0f, pA), pB);
                float p0j = SUBF(SUBF(1.0f, pB), pA);
                float siS = (p0i > 0.f) ? fmaxf(MULF(p0i,p0i), m2) : INFINITY;
                float sjS = (p0j > 0.f) ? fmaxf(MULF(p0j,p0j), m2) : INFINITY;
                bool iFirst = (di <= dj);
                float sLow  = iFirst ? siS : sjS;
                float sHigh = iFirst ? sjS : siS;
                bool pickLow = (sLow <= sHigh);
                float s = pickLow ? sLow : sHigh;
                if (s < bestS) {
                    bestS = s;
                    bool icell = pickLow ? iFirst : !iFirst;
                    if (icell) { w0 = p0i; w1 = pA; w2 = pB; o1 = ip; o2 = jp; }
                    else       { w0 = p0j; w1 = pB; w2 = pA; o1 = jp; o2 = ip; }
                }
            }
        }
    }

    if (!(bestS < INFINITY)) {   // no valid pair: reference fallback
        w0 = 0.f; w1 = 0.f; w2 = 0.f; o1 = si; o2 = si;
    }

    float* ow = out + (size_t)gid * 3;
    ow[0] = w0; ow[1] = w1; ow[2] = w2;
    float* oi = out + (size_t)V * RA * 3 + (size_t)gid * 3;
    oi[0] = (float)bi; oi[1] = (float)o1; oi[2] = (float)o2;
}

extern "C" void kernel_launch(void* const* d_in, const int* in_sizes, int n_in,
                              void* d_out, int out_size)
{
    const float* tmpl = (const float*)d_in[0];   // (5,8,2) = 80 floats
    const float* proj = (const float*)d_in[1];   // (V,16,2)
    int V = in_sizes[1] / 32;
    int total = V * 40;
    int threads = 128;
    int blocks = (total + threads - 1) / threads;
    bc_kernel<<<blocks, threads>>>(tmpl, proj, (float*)d_out, V);
}

// round 6
// speedup vs baseline: 1.8609x; 1.5049x over previous
#include <cuda_runtime.h>
#include <math.h>

// BarycentricCoordinates: V=6000 x (R*A)=40 items, N=16 projections each.
// One thread per item.
//
// Bit-exactness model (validated R4/R5, rel_err == 0.0):
//  - einsum dot products (K=2): dot = __fmaf_rn(y,y', __fmul_rn(x,x'))
//  - all other elementwise ops: strict IEEE mul/sub/div/sqrt, no contraction.
//
// R6: hot loop uses a scalar approximate score (rcp.approx on the idle MUFU
// pipe) + cheap sign-exact gates; top-2 candidates re-evaluated bit-exactly in
// the epilogue, whose operand gather now goes through shared memory (idle
// shared pipe) instead of 300+ ALU-pipe selects. dist[] dies after the
// prologue -> fewer live regs -> __launch_bounds__(128,4) for 25% occupancy.

#define MULF(a,b)   __fmul_rn((a),(b))
#define ADDF(a,b)   __fadd_rn((a),(b))
#define SUBF(a,b)   __fsub_rn((a),(b))
#define DIVF(a,b)   __fdiv_rn((a),(b))
#define DOT2(ax,ay,bx,by) __fmaf_rn((ay),(by), __fmul_rn((ax),(bx)))

__global__ __launch_bounds__(128, 4)
void bc_kernel(const float* __restrict__ tmpl,
               const float* __restrict__ proj,
               float* __restrict__ out, int V)
{
    __shared__ float2 s_e[16][128];   // (ex, ey)
    __shared__ float2 s_d[16][128];   // (d00, d02)
    __shared__ float  s_dist[16][128];

    const int RA = 40;
    int tid = threadIdx.x;
    int gid = blockIdx.x * blockDim.x + tid;
    if (gid >= V * RA) return;        // grid is exact (240000/128): never diverges
    int v  = gid / RA;
    int ra = gid - v * RA;

    float tx = __ldg(tmpl + 2 * ra);
    float ty = __ldg(tmpl + 2 * ra + 1);

    float px[16], py[16];
    const float4* pp = (const float4*)(proj + (size_t)v * 32);
    #pragma unroll
    for (int k = 0; k < 8; k++) {
        float4 q = __ldg(pp + k);
        px[2*k]   = q.x; py[2*k]   = q.y;
        px[2*k+1] = q.z; py[2*k+1] = q.w;
    }

    // dist: strict IEEE (bitwise == reference fp32 norm); stash in smem for the
    // epilogue, keep in regs only through the scan below.
    float dist[16];
    #pragma unroll
    for (int i = 0; i < 16; i++) {
        float dx = SUBF(tx, px[i]), dy = SUBF(ty, py[i]);
        dist[i] = __fsqrt_rn(ADDF(MULF(dx,dx), MULF(dy,dy)));
        s_dist[i][tid] = dist[i];
    }

    // Stable two-min scan (branchless): closest (bi,bx,by) and 2nd (si)
    float bd = dist[0], bx = px[0], by = py[0], sd = INFINITY;
    int bi = 0, si = 0;
    #pragma unroll
    for (int i = 1; i < 16; i++) {
        bool lb = dist[i] < bd;
        bool ls = dist[i] < sd;
        sd = lb ? bd : (ls ? dist[i] : sd);
        si = lb ? bi : (ls ? i       : si);
        bd = lb ? dist[i] : bd;
        bx = lb ? px[i]   : bx;
        by = lb ? py[i]   : by;
        bi = lb ? i       : bi;
    }

    float v2x = SUBF(tx, bx), v2y = SUBF(ty, by);
    float ex[16], ey[16], d00[16], d02[16];
    #pragma unroll
    for (int i = 0; i < 16; i++) {
        ex[i]  = SUBF(px[i], bx);
        ey[i]  = SUBF(py[i], by);
        d00[i] = DOT2(ex[i], ey[i], ex[i], ey[i]);
        d02[i] = DOT2(ex[i], ey[i], v2x, v2y);
        s_e[i][tid] = make_float2(ex[i], ey[i]);
        s_d[i][tid] = make_float2(d00[i], d02[i]);
    }

    // ---- approximate top-2 pair search: branch-free, scalar score ----
    float s1 = INFINITY, s2 = INFINITY;
    int   id1 = -1,      id2 = -1;

    #pragma unroll
    for (int i = 0; i < 15; i++) {
        #pragma unroll
        for (int j = i + 1; j < 16; j++) {
            float d01 = DOT2(ex[i], ey[i], ex[j], ey[j]);           // exact bits
            float den = SUBF(MULF(d00[i],d00[j]), MULF(d01,d01));   // exact bits
            den = (den == 0.0f) ? 1e-10f : den;
            float nA = SUBF(MULF(d02[i],d00[j]), MULF(d01,d02[j])); // exact bits
            float nB = SUBF(MULF(d00[i],d02[j]), MULF(d01,d02[i])); // exact bits
            float p0n  = SUBF(SUBF(den, nA), nB);     // ~ p0 * den (approx ok)
            float den2 = den * den;
            // sign-exact gates via products; conservative margin on p0
            float gA = nA * den;
            float gB = nB * den;
            float gP = __fmaf_rn(p0n, den, 1e-5f * den2);
            float m  = fminf(fminf(gA, gB), gP);
            float sNum = fmaxf(fmaxf(nA*nA, nB*nB), p0n*p0n);
            float r;
            asm("rcp.approx.f32 %0, %1;" : "=f"(r) : "f"(den2));    // MUFU pipe
            float s = sNum * r;
            s = (m > 0.0f) ? s : INFINITY;
            int code = i * 16 + j;
            bool b1 = s < s1;
            bool b2 = s < s2;
            s2  = b1 ? s1  : (b2 ? s    : s2);
            id2 = b1 ? id1 : (b2 ? code : id2);
            s1  = b1 ? s   : s1;
            id1 = b1 ? code : id1;
        }
    }

    // ---- exact epilogue: re-evaluate top-2 candidates bit-exactly ----
    float w0 = 0.f, w1 = 0.f, w2 = 0.f;
    int   o1 = si, o2 = si;
    float bestS = INFINITY;

    #pragma unroll
    for (int c = 0; c < 2; c++) {
        int code = (c == 0) ? id1 : id2;
        if (code >= 0) {
            int ip = code >> 4, jp = code & 15;
            float2 eiv = s_e[ip][tid], ejv = s_e[jp][tid];
            float2 div = s_d[ip][tid], djv = s_d[jp][tid];
            float  di  = s_dist[ip][tid], dj = s_dist[jp][tid];
            float d01 = DOT2(eiv.x, eiv.y, ejv.x, ejv.y);
            float den = SUBF(MULF(div.x,djv.x), MULF(d01,d01));
            if (den == 0.0f) den = 1e-10f;
            float nA = SUBF(MULF(div.y,djv.x), MULF(d01,djv.y));
            float nB = SUBF(MULF(div.x,djv.y), MULF(d01,div.y));
            bool candx = (den > 0.0f) ? (nA > 0.0f && nB > 0.0f)
                                      : (nA < 0.0f && nB < 0.0f);
            if (candx) {
                float pA = DIVF(nA, den);                 // exact IEEE divide
                float pB = DIVF(nB, den);
                float m2  = fmaxf(MULF(pA,pA), MULF(pB,pB));
                float p0i = SUBF(SUBF(1.0f, pA), pB);
                float p0j = SUBF(SUBF(1.0f, pB), pA);
                float siS = (p0i > 0.f) ? fmaxf(MULF(p0i,p0i), m2) : INFINITY;
                float sjS = (p0j > 0.f) ? fmaxf(MULF(p0j,p0j), m2) : INFINITY;
                bool iFirst = (di <= dj);
                float sLow  = iFirst ? siS : sjS;
                float sHigh = iFirst ? sjS : siS;
                bool pickLow = (sLow <= sHigh);
                float s = pickLow ? sLow : sHigh;
                if (s < bestS) {
                    bestS = s;
                    bool icell = pickLow ? iFirst : !iFirst;
                    if (icell) { w0 = p0i; w1 = pA; w2 = pB; o1 = ip; o2 = jp; }
                    else       { w0 = p0j; w1 = pB; w2 = pA; o1 = jp; o2 = ip; }
                }
            }
        }
    }

    if (!(bestS < INFINITY)) {   // no valid pair: reference fallback
        w0 = 0.f; w1 = 0.f; w2 = 0.f; o1 = si; o2 = si;
    }

    float* ow = out + (size_t)gid * 3;
    ow[0] = w0; ow[1] = w1; ow[2] = w2;
    float* oi = out + (size_t)V * RA * 3 + (size_t)gid * 3;
    oi[0] = (float)bi; oi[1] = (float)o1; oi[2] = (float)o2;
}

extern "C" void kernel_launch(void* const* d_in, const int* in_sizes, int n_in,
                              void* d_out, int out_size)
{
    const float* tmpl = (const float*)d_in[0];   // (5,8,2) = 80 floats
    const float* proj = (const float*)d_in[1];   // (V,16,2)
    int V = in_sizes[1] / 32;
    int total = V * 40;
    int threads = 128;
    int blocks = (total + threads - 1) / threads;
    bc_kernel<<<blocks, threads>>>(tmpl, proj, (float*)d_out, V);
}